// round 3
// baseline (speedup 1.0000x reference)
#include <cuda_runtime.h>
#include <math.h>

#define NN 50000
#define NE 800000
#define NG 1024
#define IND 25
#define DIM 64
#define STEPS 3

// ---------------- device scratch (statically allocated; no cudaMalloc) ------
__device__ float g_hw[NN * DIM];      // h @ Wc  (post lin0+relu, pre-aggregation)
__device__ float g_agg[NN * DIM];     // GCN aggregation accumulator
__device__ float g_h2[NN * DIM];      // relu(agg + bc)  -> set2set input
__device__ float g_dinv[NN];
__device__ int   g_deg[NN];
__device__ int   g_gcnt[NG];
__device__ int   g_goff[NG + 1];
__device__ float g_hs[NG * DIM];
__device__ float g_cs[NG * DIM];
__device__ float g_qstar[NG * 2 * DIM];
__device__ float g_gates[NG * 4 * DIM];

// ---------------- init: zero states, deg=1 (self loop), gcnt=0 -------------
__global__ void k_init() {
    int t = blockIdx.x * 256 + threadIdx.x;          // grid covers 131072
    if (t < NG * DIM)     { g_hs[t] = 0.f; g_cs[t] = 0.f; }
    if (t < NG * 2 * DIM) g_qstar[t] = 0.f;
    if (t < NG)           g_gcnt[t] = 0;
    if (t < NN)           g_deg[t] = 1;
}

// ---------------- fused lin0(+relu) and @Wc --------------------------------
__global__ void k_lin0(const float* __restrict__ x, const float* __restrict__ W0,
                       const float* __restrict__ b0, const float* __restrict__ Wc) {
    __shared__ float sW0[IND * DIM];
    __shared__ float sWc[DIM * DIM];
    __shared__ float sb0[DIM];
    __shared__ float sx[4][IND];
    __shared__ float sh[4][DIM];
    int tid = threadIdx.x;                           // 256 threads
    for (int i = tid; i < IND * DIM; i += 256) sW0[i] = W0[i];
    for (int i = tid; i < DIM * DIM; i += 256) sWc[i] = Wc[i];
    if (tid < DIM) sb0[tid] = b0[tid];
    __syncthreads();
    int d = tid & 63, ln = tid >> 6;                 // 4 nodes per iteration
    for (int base = blockIdx.x * 4; base < NN; base += gridDim.x * 4) {
        for (int i = tid; i < 4 * IND; i += 256) {
            int nn = i / IND, kk = i % IND;
            int node = base + nn;
            sx[nn][kk] = (node < NN) ? x[node * IND + kk] : 0.f;
        }
        __syncthreads();
        float acc = sb0[d];
        #pragma unroll
        for (int k = 0; k < IND; k++) acc += sx[ln][k] * sW0[k * DIM + d];
        sh[ln][d] = fmaxf(acc, 0.f);
        __syncthreads();
        float acc2 = 0.f;
        #pragma unroll
        for (int k = 0; k < DIM; k++) acc2 += sh[ln][k] * sWc[k * DIM + d];
        int node = base + ln;
        if (node < NN) g_hw[node * DIM + d] = acc2;
        __syncthreads();
    }
}

// ---------------- degree histogram (targets) -------------------------------
__global__ void k_deg_hist(const int* __restrict__ ei) {
    int t = blockIdx.x * 256 + threadIdx.x;
    if (t < NE) atomicAdd(&g_deg[ei[NE + t]], 1);
}

// ---------------- batch histogram ------------------------------------------
__global__ void k_bat_hist(const int* __restrict__ batch) {
    int t = blockIdx.x * 256 + threadIdx.x;
    if (t < NN) atomicAdd(&g_gcnt[batch[t]], 1);
}

// ---------------- scan over graph counts -> offsets -------------------------
__global__ void k_scan() {
    __shared__ int s[NG];
    int t = threadIdx.x;
    s[t] = g_gcnt[t];
    __syncthreads();
    for (int off = 1; off < NG; off <<= 1) {
        int v = (t >= off) ? s[t - off] : 0;
        __syncthreads();
        s[t] += v;
        __syncthreads();
    }
    g_goff[t + 1] = s[t];
    if (t == 0) g_goff[0] = 0;
}

// ---------------- dinv = rsqrt(deg) -----------------------------------------
__global__ void k_dinv() {
    int t = blockIdx.x * 256 + threadIdx.x;
    if (t < NN) g_dinv[t] = rsqrtf((float)g_deg[t]);
}

// ---------------- agg init with self-loop term ------------------------------
__global__ void k_self() {
    int t = blockIdx.x * 256 + threadIdx.x;          // NN*16 threads
    if (t >= NN * 16) return;
    int n = t >> 4;
    float s = g_dinv[n]; s *= s;
    float4 v = ((const float4*)g_hw)[t];
    v.x *= s; v.y *= s; v.z *= s; v.w *= s;
    ((float4*)g_agg)[t] = v;
}

// ---------------- edge scatter: agg[col] += hw[row]*norm --------------------
__global__ void k_scatter(const int* __restrict__ ei) {
    int t = blockIdx.x * 256 + threadIdx.x;          // NE*16 threads exactly
    int e = t >> 4;
    if (e >= NE) return;
    int q = t & 15;
    int r = ei[e];
    int c = ei[NE + e];
    float norm = g_dinv[r] * g_dinv[c];
    float4 v = ((const float4*)g_hw)[r * 16 + q];
    float* dst = &g_agg[c * DIM + q * 4];
    asm volatile("red.global.add.v4.f32 [%0], {%1, %2, %3, %4};"
                 :: "l"(dst), "f"(v.x * norm), "f"(v.y * norm),
                    "f"(v.z * norm), "f"(v.w * norm) : "memory");
}

// ---------------- h2 = relu(agg + bc) ---------------------------------------
__global__ void k_h2(const float* __restrict__ bc) {
    int t = blockIdx.x * 256 + threadIdx.x;
    if (t >= NN * 16) return;
    float4 a = ((const float4*)g_agg)[t];
    float4 b = ((const float4*)bc)[t & 15];
    a.x = fmaxf(a.x + b.x, 0.f);
    a.y = fmaxf(a.y + b.y, 0.f);
    a.z = fmaxf(a.z + b.z, 0.f);
    a.w = fmaxf(a.w + b.w, 0.f);
    ((float4*)g_h2)[t] = a;
}

// ---------------- LSTM gates: gates = qstar@Wih^T + hs@Whh^T + b -----------
// grid (32, 8): blockIdx.x -> 32 graphs, blockIdx.y -> 32 gate rows.
__global__ void k_gates(const float* __restrict__ Wih, const float* __restrict__ Whh,
                        const float* __restrict__ bih, const float* __restrict__ bhh) {
    __shared__ float sq[32][129];
    __shared__ float shh[32][65];
    int g0 = blockIdx.x * 32;
    int j0 = blockIdx.y * 32;
    int tid = threadIdx.x;                           // 256
    for (int i = tid; i < 32 * 128; i += 256) {
        int g = i >> 7, k = i & 127;
        sq[g][k] = g_qstar[(g0 + g) * 128 + k];
    }
    for (int i = tid; i < 32 * 64; i += 256) {
        int g = i >> 6, k = i & 63;
        shh[g][k] = g_hs[(g0 + g) * 64 + k];
    }
    __syncthreads();
    int warp = tid >> 5, lane = tid & 31;            // lane = graph
    for (int jj = warp; jj < 32; jj += 8) {
        int j = j0 + jj;
        const float4* wi4 = (const float4*)(Wih + j * 128);
        const float2* wh2 = (const float2*)(Whh + j * 64);
        float acc = bih[j] + bhh[j];
        #pragma unroll
        for (int k4 = 0; k4 < 32; k4++) {
            float4 w = wi4[k4];
            acc += w.x * sq[lane][k4 * 4 + 0] + w.y * sq[lane][k4 * 4 + 1]
                 + w.z * sq[lane][k4 * 4 + 2] + w.w * sq[lane][k4 * 4 + 3];
        }
        #pragma unroll
        for (int k2 = 0; k2 < 32; k2++) {
            float2 w = wh2[k2];
            acc += w.x * shh[lane][k2 * 2 + 0] + w.y * shh[lane][k2 * 2 + 1];
        }
        g_gates[(g0 + lane) * 256 + j] = acc;
    }
}

// ---------------- LSTM cell update ------------------------------------------
__global__ void k_cell() {
    int t = blockIdx.x * 256 + threadIdx.x;
    if (t >= NG * DIM) return;
    int g = t >> 6, d = t & 63;
    const float* gt = g_gates + g * 256;
    float i = 1.f / (1.f + __expf(-gt[d]));
    float f = 1.f / (1.f + __expf(-gt[64 + d]));
    float gg = tanhf(gt[128 + d]);
    float o = 1.f / (1.f + __expf(-gt[192 + d]));
    float c = f * g_cs[t] + i * gg;
    float h = o * tanhf(c);
    g_cs[t] = c;
    g_hs[t] = h;
}

// ---------------- per-graph attention + pooled r; writes q_star -------------
// one block per graph, 128 threads (4 warps). batch is sorted -> [goff[g], goff[g+1])
__global__ void k_attn() {
    int g = blockIdx.x;
    int tid = threadIdx.x;
    int warp = tid >> 5, lane = tid & 31;
    __shared__ float sqv[DIM];
    __shared__ float smax[4];
    __shared__ float ssum;
    __shared__ float sr[DIM];
    if (tid < DIM) { sqv[tid] = g_hs[g * DIM + tid]; sr[tid] = 0.f; }
    if (tid == 0) ssum = 0.f;
    __syncthreads();
    int start = g_goff[g], end = g_goff[g + 1];
    float q2x = sqv[lane * 2], q2y = sqv[lane * 2 + 1];
    // pass 1: segment max
    float lmax = -1e30f;
    for (int v = start + warp; v < end; v += 4) {
        float2 hv = ((const float2*)g_h2)[v * 32 + lane];
        float d = hv.x * q2x + hv.y * q2y;
        d += __shfl_xor_sync(0xffffffffu, d, 16);
        d += __shfl_xor_sync(0xffffffffu, d, 8);
        d += __shfl_xor_sync(0xffffffffu, d, 4);
        d += __shfl_xor_sync(0xffffffffu, d, 2);
        d += __shfl_xor_sync(0xffffffffu, d, 1);
        lmax = fmaxf(lmax, d);
    }
    if (lane == 0) smax[warp] = lmax;
    __syncthreads();
    float m = fmaxf(fmaxf(smax[0], smax[1]), fmaxf(smax[2], smax[3]));
    // pass 2: exp-sum and weighted accumulation (segment data now L1-hot)
    float lsum = 0.f, rx = 0.f, ry = 0.f;
    for (int v = start + warp; v < end; v += 4) {
        float2 hv = ((const float2*)g_h2)[v * 32 + lane];
        float d = hv.x * q2x + hv.y * q2y;
        d += __shfl_xor_sync(0xffffffffu, d, 16);
        d += __shfl_xor_sync(0xffffffffu, d, 8);
        d += __shfl_xor_sync(0xffffffffu, d, 4);
        d += __shfl_xor_sync(0xffffffffu, d, 2);
        d += __shfl_xor_sync(0xffffffffu, d, 1);
        float t = __expf(d - m);
        lsum += t;
        rx += t * hv.x;
        ry += t * hv.y;
    }
    if (lane == 0) atomicAdd(&ssum, lsum);
    atomicAdd(&sr[lane * 2], rx);
    atomicAdd(&sr[lane * 2 + 1], ry);
    __syncthreads();
    if (tid < DIM) {
        float r = (end > start) ? sr[tid] / ssum : 0.f;   // empty graph -> r = 0
        g_qstar[g * 128 + tid] = sqv[tid];
        g_qstar[g * 128 + DIM + tid] = r;
    }
}

// ---------------- readout: relu(qstar@W1+b1)@W2 + b2 ------------------------
__global__ void k_readout(const float* __restrict__ W1, const float* __restrict__ b1,
                          const float* __restrict__ W2, const float* __restrict__ b2,
                          float* __restrict__ out) {
    int g = blockIdx.x;
    int d = threadIdx.x;                             // 64
    __shared__ float sq[128];
    __shared__ float red[64];
    sq[d] = g_qstar[g * 128 + d];
    sq[64 + d] = g_qstar[g * 128 + 64 + d];
    __syncthreads();
    float acc = b1[d];
    #pragma unroll
    for (int k = 0; k < 128; k++) acc += sq[k] * W1[k * 64 + d];
    acc = fmaxf(acc, 0.f) * W2[d];
    red[d] = acc;
    __syncthreads();
    for (int s = 32; s > 0; s >>= 1) {
        if (d < s) red[d] += red[d + s];
        __syncthreads();
    }
    if (d == 0) out[g] = red[0] + b2[0];
}

// ---------------- launch sequence -------------------------------------------
extern "C" void kernel_launch(void* const* d_in, const int* in_sizes, int n_in,
                              void* d_out, int out_size) {
    const float* x     = (const float*)d_in[0];
    const int*   ei    = (const int*)  d_in[1];
    const int*   batch = (const int*)  d_in[2];
    const float* W0    = (const float*)d_in[3];
    const float* b0    = (const float*)d_in[4];
    const float* Wc    = (const float*)d_in[5];
    const float* bc    = (const float*)d_in[6];
    const float* Wih   = (const float*)d_in[7];
    const float* Whh   = (const float*)d_in[8];
    const float* bih   = (const float*)d_in[9];
    const float* bhh   = (const float*)d_in[10];
    const float* W1    = (const float*)d_in[11];
    const float* b1    = (const float*)d_in[12];
    const float* W2    = (const float*)d_in[13];
    const float* b2    = (const float*)d_in[14];
    float* out = (float*)d_out;

    k_init<<<512, 256>>>();
    k_lin0<<<512, 256>>>(x, W0, b0, Wc);
    k_deg_hist<<<(NE + 255) / 256, 256>>>(ei);
    k_bat_hist<<<(NN + 255) / 256, 256>>>(batch);
    k_scan<<<1, NG>>>();
    k_dinv<<<(NN + 255) / 256, 256>>>();
    k_self<<<(NN * 16) / 256 + 1, 256>>>();
    k_scatter<<<(NE * 16) / 256, 256>>>(ei);
    k_h2<<<(NN * 16) / 256 + 1, 256>>>(bc);
    for (int s = 0; s < STEPS; s++) {
        k_gates<<<dim3(32, 8), 256>>>(Wih, Whh, bih, bhh);
        k_cell<<<(NG * DIM) / 256, 256>>>();
        k_attn<<<NG, 128>>>();
    }
    k_readout<<<NG, 64>>>(W1, b1, W2, b2, out);
}